// round 2
// baseline (speedup 1.0000x reference)
#include <cuda_runtime.h>
#include <math.h>

// ============================================================================
// EnsembleRatioModel — round 1 baseline
//
// Structure: chain of fused (ReLU-on-load) GEMM+bias kernels + a final
// dot/sigmoid/mask kernel. All fp32, with Blackwell packed fma.rn.f32x2
// (FFMA2) accumulators to double the scalar-fp32 FLOP rate.
//
// Output packing assumption (float32, concatenated flat, reference order):
//   [0,          N*512)  repr_                 [N, 512]
//   [N*512,      +3N)    r_hat * mask          [P, N] (p-major)
//   [N*512+3N,   +3N)    s_hat * mask          [P, N]
//   [N*512+6N,   +3N)    mask (1.0 / 0.0)      [P, N]
// ============================================================================

#define GN 131072
#define BM 128
#define BN 128
#define BK 8
#define TM 8
#define TN 8

// Scratch activations (ping-pong), 256 MB each. Static __device__ arrays per
// the allocation rules.
__device__ float g_bufA[67108864];   // [N, 512]
__device__ float g_bufB[67108864];   // [N, 512] (only [N,256] used for sub layer 1)

// ---- packed f32x2 helpers (Blackwell FFMA2 path) ---------------------------
__device__ __forceinline__ unsigned long long pack2(float a, float b) {
    unsigned long long r;
    asm("mov.b64 %0, {%1, %2};" : "=l"(r) : "f"(a), "f"(b));
    return r;
}
__device__ __forceinline__ float2 unpack2(unsigned long long v) {
    float2 f;
    asm("mov.b64 {%0, %1}, %2;" : "=f"(f.x), "=f"(f.y) : "l"(v));
    return f;
}
__device__ __forceinline__ void fma2(unsigned long long& d,
                                     unsigned long long a,
                                     unsigned long long b) {
    asm("fma.rn.f32x2 %0, %1, %2, %0;" : "+l"(d) : "l"(a), "l"(b));
}

// ---- C[M,N] = relu(A[M,K]) @ W[K,N] + bias[N] -------------------------------
// A row-major [M,K], W row-major [K,N]. M % 128 == 0, N % 128 == 0, K % 8 == 0.
__global__ void __launch_bounds__(256, 2)
gemm_relu_bias(const float* __restrict__ A, const float* __restrict__ W,
               const float* __restrict__ bias, float* __restrict__ C,
               int M, int N, int K)
{
    __shared__ float As[BK][BM];   // A tile, transposed, ReLU applied
    __shared__ float Ws[BK][BN];

    const int tid = threadIdx.x;
    const int tx  = tid & 15;        // 0..15  -> output col group
    const int ty  = tid >> 4;        // 0..15  -> output row group
    const int bm  = blockIdx.y * BM;
    const int bn  = blockIdx.x * BN;

    // global->shared load mapping
    const int arow = tid >> 1;          // 0..127
    const int acol = (tid & 1) << 2;    // 0 or 4
    const int wrow = tid >> 5;          // 0..7
    const int wcol = (tid & 31) << 2;   // 0..124

    const float* Ap = A + (size_t)(bm + arow) * K + acol;
    const float* Wp = W + (size_t)wrow * N + bn + wcol;

    unsigned long long acc[TM][TN / 2];
#pragma unroll
    for (int i = 0; i < TM; i++)
#pragma unroll
        for (int j = 0; j < TN / 2; j++) acc[i][j] = 0ull;

    for (int k0 = 0; k0 < K; k0 += BK) {
        float4 av = *(const float4*)(Ap + k0);
        As[acol + 0][arow] = fmaxf(av.x, 0.f);
        As[acol + 1][arow] = fmaxf(av.y, 0.f);
        As[acol + 2][arow] = fmaxf(av.z, 0.f);
        As[acol + 3][arow] = fmaxf(av.w, 0.f);
        *(float4*)&Ws[wrow][wcol] = *(const float4*)(Wp + (size_t)k0 * N);
        __syncthreads();

#pragma unroll
        for (int k = 0; k < BK; k++) {
            float4 a0 = *(const float4*)&As[k][ty * TM];
            float4 a1 = *(const float4*)&As[k][ty * TM + 4];
            const ulonglong2* wp2 = (const ulonglong2*)&Ws[k][tx * TN];
            ulonglong2 w01 = wp2[0];
            ulonglong2 w23 = wp2[1];
            unsigned long long rb[4] = {w01.x, w01.y, w23.x, w23.y};
            float ra[TM] = {a0.x, a0.y, a0.z, a0.w, a1.x, a1.y, a1.z, a1.w};
#pragma unroll
            for (int i = 0; i < TM; i++) {
                unsigned long long a2 = pack2(ra[i], ra[i]);
#pragma unroll
                for (int j = 0; j < TN / 2; j++) fma2(acc[i][j], a2, rb[j]);
            }
        }
        __syncthreads();
    }

    float bv[TN];
#pragma unroll
    for (int j = 0; j < TN; j++) bv[j] = bias[bn + tx * TN + j];

#pragma unroll
    for (int i = 0; i < TM; i++) {
        float2 p0 = unpack2(acc[i][0]);
        float2 p1 = unpack2(acc[i][1]);
        float2 p2 = unpack2(acc[i][2]);
        float2 p3 = unpack2(acc[i][3]);
        size_t off = (size_t)(bm + ty * TM + i) * N + bn + tx * TN;
        float4 v0 = make_float4(p0.x + bv[0], p0.y + bv[1], p1.x + bv[2], p1.y + bv[3]);
        float4 v1 = make_float4(p2.x + bv[4], p2.y + bv[5], p3.x + bv[6], p3.y + bv[7]);
        *(float4*)(C + off)     = v0;
        *(float4*)(C + off + 4) = v1;
    }
}

// ---- final: logit = relu(s1) . SW2[p] + Sb2[p]; sigmoid/clip/ratio/mask -----
__global__ void subnet_final(const float* __restrict__ s1,      // [N, 256]
                             const float* __restrict__ SW2,     // [3, 256]
                             const float* __restrict__ Sb2,     // [3]
                             const int*   __restrict__ y,       // [N]
                             const int*   __restrict__ pairs,   // [3, 2]
                             int p,
                             float* __restrict__ out_r,
                             float* __restrict__ out_s,
                             float* __restrict__ out_m,
                             int Nrows)
{
    __shared__ float w[256];
    const int tid = threadIdx.x;
    w[tid] = SW2[p * 256 + tid];
    __syncthreads();

    const float sb = Sb2[p];
    const int pa = pairs[2 * p + 0];
    const int pb = pairs[2 * p + 1];

    const int lane = tid & 31;
    const int warp = tid >> 5;
    const int warps_per_blk = blockDim.x >> 5;
    const int gw = blockIdx.x * warps_per_blk + warp;
    const int warps_total = gridDim.x * warps_per_blk;

    for (int n = gw; n < Nrows; n += warps_total) {
        const float* row = s1 + (size_t)n * 256;
        float acc = 0.f;
#pragma unroll
        for (int j = 0; j < 8; j++) {
            int c = lane + 32 * j;
            acc += fmaxf(row[c], 0.f) * w[c];
        }
#pragma unroll
        for (int o = 16; o > 0; o >>= 1)
            acc += __shfl_xor_sync(0xFFFFFFFFu, acc, o);

        if (lane == 0) {
            float logit = acc + sb;
            float s = 1.f / (1.f + expf(-logit));
            s = fmaxf(s, 1e-9f);
            float r = (1.f - s) / s;
            int yv = y[n];
            float m = (yv == pa || yv == pb) ? 1.f : 0.f;
            out_r[n] = r * m;
            out_s[n] = s * m;
            out_m[n] = m;
        }
    }
}

// ============================================================================
extern "C" void kernel_launch(void* const* d_in, const int* in_sizes, int n_in,
                              void* d_out, int out_size)
{
    const float* x     = (const float*)d_in[0];
    const int*   y     = (const int*)  d_in[1];
    const int*   pairs = (const int*)  d_in[2];
    const float* W0    = (const float*)d_in[3];
    const float* b0    = (const float*)d_in[4];
    const float* W1    = (const float*)d_in[5];
    const float* b1    = (const float*)d_in[6];
    const float* W2    = (const float*)d_in[7];
    const float* b2    = (const float*)d_in[8];
    const float* SW0   = (const float*)d_in[9];
    const float* Sb0   = (const float*)d_in[10];
    const float* SW1   = (const float*)d_in[11];
    const float* Sb1   = (const float*)d_in[12];
    const float* SW2   = (const float*)d_in[13];
    const float* Sb2   = (const float*)d_in[14];

    const int M = GN;
    float* out   = (float*)d_out;
    float* repr  = out;                                  // [N, 512]
    float* r_seg = out + (size_t)M * 512;                // [3, N]
    float* s_seg = r_seg + 3 * (size_t)M;                // [3, N]
    float* m_seg = s_seg + 3 * (size_t)M;                // [3, N]

    float *bufA = nullptr, *bufB = nullptr;
    cudaGetSymbolAddress((void**)&bufA, g_bufA);
    cudaGetSymbolAddress((void**)&bufB, g_bufB);

    dim3 blk(256);
    dim3 g512(512 / BN, M / BM);   // (4, 1024)
    dim3 g256(256 / BN, M / BM);   // (2, 1024)

    // trunk
    gemm_relu_bias<<<g512, blk>>>(x,    W0, b0, bufA, M, 512, 64);
    gemm_relu_bias<<<g512, blk>>>(bufA, W1, b1, bufB, M, 512, 512);
    gemm_relu_bias<<<g512, blk>>>(bufB, W2, b2, repr, M, 512, 512);

    // per-pair subnetworks
    for (int p = 0; p < 3; p++) {
        gemm_relu_bias<<<g512, blk>>>(repr, SW0 + (size_t)p * 512 * 512,
                                      Sb0 + p * 512, bufA, M, 512, 512);
        gemm_relu_bias<<<g256, blk>>>(bufA, SW1 + (size_t)p * 512 * 256,
                                      Sb1 + p * 256, bufB, M, 256, 512);
        subnet_final<<<512, 256>>>(bufB, SW2, Sb2, y, pairs, p,
                                   r_seg + (size_t)p * M,
                                   s_seg + (size_t)p * M,
                                   m_seg + (size_t)p * M, M);
    }
}

// round 5
// speedup vs baseline: 2.3304x; 2.3304x over previous
#include <cuda_runtime.h>
#include <cuda_bf16.h>
#include <cstdint>
#include <math.h>

// ============================================================================
// EnsembleRatioModel — round 4: bf16-split (3xBF16 ~ fp32) GEMM chain on the
// LEGACY tensor-core path (mma.sync.m16n8k16), since the toolchain targets
// plain sm_100 (no 'a' features: tcgen05 rejected by ptxas in round 3).
//
// C = relu(A) @ W + b  computed as  A_hi@W_hi + A_hi@W_lo + A_lo@W_hi with
// fp32 register accumulation. Activations stored as bf16 (hi,lo) pairs by
// each layer's epilogue; repr_ additionally written raw fp32.
//
// Output packing (validated round 1):
//   [0, N*512)  repr_ ; then [3N) r_hat*mask ; [3N) s_hat*mask ; [3N) mask
// ============================================================================

#define GN 131072

// ---------------- device scratch (static globals; no allocation) ------------
__device__ unsigned short g_hiA[GN * 512];
__device__ unsigned short g_loA[GN * 512];
__device__ unsigned short g_hiB[GN * 512];
__device__ unsigned short g_loB[GN * 512];
__device__ unsigned short g_hiC[GN * 256];
__device__ unsigned short g_loC[GN * 256];
__device__ unsigned short g_hiX[GN * 64];
__device__ unsigned short g_loX[GN * 64];
__device__ unsigned short g_whi[1736704];
__device__ unsigned short g_wlo[1736704];

#define OFF_W0   0u
#define OFF_W1   32768u
#define OFF_W2   294912u
#define OFF_SW0  557056u      /* + p*262144 */
#define OFF_SW1  1343488u     /* + p*131072 */

// ---------------- helpers ----------------------------------------------------
__device__ __forceinline__ uint32_t smem_u32(const void* p) {
    uint32_t a;
    asm("{ .reg .u64 t; cvta.to.shared.u64 t, %1; cvt.u32.u64 %0, t; }"
        : "=r"(a) : "l"(p));
    return a;
}
__device__ __forceinline__ void cpasync16(uint32_t dst, const void* src) {
    asm volatile("cp.async.cg.shared.global [%0], [%1], 16;"
                 :: "r"(dst), "l"(src) : "memory");
}
__device__ __forceinline__ void mma_bf16(float* d, const uint32_t* a,
                                         const uint32_t* b) {
    asm volatile(
        "mma.sync.aligned.m16n8k16.row.col.f32.bf16.bf16.f32 "
        "{%0,%1,%2,%3}, {%4,%5,%6,%7}, {%8,%9}, {%0,%1,%2,%3};"
        : "+f"(d[0]), "+f"(d[1]), "+f"(d[2]), "+f"(d[3])
        : "r"(a[0]), "r"(a[1]), "r"(a[2]), "r"(a[3]), "r"(b[0]), "r"(b[1]));
}
__device__ __forceinline__ void split_bf16(float v, __nv_bfloat16& h, __nv_bfloat16& l) {
    h = __float2bfloat16(v);
    l = __float2bfloat16(v - __bfloat162float(h));
}

// ============================================================================
// GEMM: C[M,Ntot] = (Ahi+Alo)[M,K] @ (Whi+Wlo)^T   (W stored [Ntot,K])
// 128x128 CTA tile, 256 threads, warp tile 64x32, K-chunk 32, double buffer.
// SMEM per stage: 4 components x 128 rows x 40 bf16 (pitch 80B) = 40960 B.
// ============================================================================
#define STAGE_BYTES 40960
#define COMP_BYTES  10240
#define ROW_PITCH   80

__global__ void __launch_bounds__(256)
gemm_mma(const __nv_bfloat16* __restrict__ Ahi, const __nv_bfloat16* __restrict__ Alo,
         const __nv_bfloat16* __restrict__ Whi, const __nv_bfloat16* __restrict__ Wlo,
         const float* __restrict__ bias,
         float* __restrict__ raw_out,
         __nv_bfloat16* __restrict__ Ohi, __nv_bfloat16* __restrict__ Olo,
         int K, int Ntot, int write_raw)
{
    extern __shared__ __align__(16) char smem[];
    const uint32_t smem_base = smem_u32(smem);

    const int tid   = threadIdx.x;
    const int wid   = tid >> 5;
    const int lane  = tid & 31;
    const int g     = lane >> 2;      // group id (row within 8)
    const int tk    = lane & 3;       // thread-in-group (k/col pairs)
    const int warpM = wid >> 2;       // 0..1 -> 64-row half
    const int warpN = wid & 3;        // 0..3 -> 32-col quarter
    const int m0 = blockIdx.y * 128;
    const int n0 = blockIdx.x * 128;

    const int nk = K >> 5;            // K-chunks of 32

    // ---- chunk loader: 2048 cp.async x16B per chunk, 8 per thread ----------
    auto load_chunk = [&](int c, int s) {
        const uint32_t st = smem_base + (uint32_t)s * STAGE_BYTES;
        const int koff = c * 32;
#pragma unroll
        for (int i = 0; i < 8; i++) {
            int idx  = i * 256 + tid;
            int comp = idx >> 9;          // 0:Ahi 1:Alo 2:Whi 3:Wlo
            int rem  = idx & 511;
            int row  = rem >> 2;
            int seg  = rem & 3;
            uint32_t dst = st + (uint32_t)comp * COMP_BYTES
                         + (uint32_t)row * ROW_PITCH + (uint32_t)seg * 16;
            const __nv_bfloat16* src;
            size_t roff;
            if (comp == 0)      { src = Ahi; roff = (size_t)(m0 + row) * K; }
            else if (comp == 1) { src = Alo; roff = (size_t)(m0 + row) * K; }
            else if (comp == 2) { src = Whi; roff = (size_t)(n0 + row) * K; }
            else                { src = Wlo; roff = (size_t)(n0 + row) * K; }
            cpasync16(dst, src + roff + koff + seg * 8);
        }
        asm volatile("cp.async.commit_group;" ::: "memory");
    };

    float acc[4][4][4];
#pragma unroll
    for (int i = 0; i < 4; i++)
#pragma unroll
        for (int j = 0; j < 4; j++)
#pragma unroll
            for (int r = 0; r < 4; r++) acc[i][j][r] = 0.f;

    load_chunk(0, 0);

    for (int c = 0; c < nk; c++) {
        if (c + 1 < nk) {
            load_chunk(c + 1, (c + 1) & 1);
            asm volatile("cp.async.wait_group 1;" ::: "memory");
        } else {
            asm volatile("cp.async.wait_group 0;" ::: "memory");
        }
        __syncthreads();

        const char* sb = smem + (size_t)(c & 1) * STAGE_BYTES;

#pragma unroll
        for (int t = 0; t < 2; t++) {
            const int kb = t * 32;    // byte offset of k16 step within row

            // B fragments (hi and lo)
            uint32_t bh[4][2], bl[4][2];
#pragma unroll
            for (int j = 0; j < 4; j++) {
                int n = warpN * 32 + j * 8 + g;
                const char* pb = sb + 2 * COMP_BYTES + n * ROW_PITCH + kb + tk * 4;
                bh[j][0] = *(const uint32_t*)pb;
                bh[j][1] = *(const uint32_t*)(pb + 16);
                bl[j][0] = *(const uint32_t*)(pb + COMP_BYTES);
                bl[j][1] = *(const uint32_t*)(pb + COMP_BYTES + 16);
            }
            // A hi fragments
            uint32_t ah[4][4];
#pragma unroll
            for (int i = 0; i < 4; i++) {
                int r = warpM * 64 + i * 16 + g;
                const char* pa = sb + r * ROW_PITCH + kb + tk * 4;
                ah[i][0] = *(const uint32_t*)pa;
                ah[i][1] = *(const uint32_t*)(pa + 8 * ROW_PITCH);
                ah[i][2] = *(const uint32_t*)(pa + 16);
                ah[i][3] = *(const uint32_t*)(pa + 8 * ROW_PITCH + 16);
            }
            // hi*hi and hi*lo
#pragma unroll
            for (int i = 0; i < 4; i++)
#pragma unroll
                for (int j = 0; j < 4; j++) {
                    mma_bf16(acc[i][j], ah[i], bh[j]);
                    mma_bf16(acc[i][j], ah[i], bl[j]);
                }
            // A lo fragments, lo*hi
            uint32_t al[4][4];
#pragma unroll
            for (int i = 0; i < 4; i++) {
                int r = warpM * 64 + i * 16 + g;
                const char* pa = sb + COMP_BYTES + r * ROW_PITCH + kb + tk * 4;
                al[i][0] = *(const uint32_t*)pa;
                al[i][1] = *(const uint32_t*)(pa + 8 * ROW_PITCH);
                al[i][2] = *(const uint32_t*)(pa + 16);
                al[i][3] = *(const uint32_t*)(pa + 8 * ROW_PITCH + 16);
            }
#pragma unroll
            for (int i = 0; i < 4; i++)
#pragma unroll
                for (int j = 0; j < 4; j++)
                    mma_bf16(acc[i][j], al[i], bh[j]);
        }
        __syncthreads();
    }

    // ---- epilogue: bias, optional raw fp32, relu, bf16 hi/lo split ---------
#pragma unroll
    for (int j = 0; j < 4; j++) {
        const int cc = n0 + warpN * 32 + j * 8 + tk * 2;
        const float b0v = bias[cc];
        const float b1v = bias[cc + 1];
#pragma unroll
        for (int i = 0; i < 4; i++) {
            const int r0 = m0 + warpM * 64 + i * 16 + g;
#pragma unroll
            for (int half = 0; half < 2; half++) {
                const int r = r0 + half * 8;
                float v0 = acc[i][j][half * 2 + 0] + b0v;
                float v1 = acc[i][j][half * 2 + 1] + b1v;
                const size_t off = (size_t)r * Ntot + cc;
                if (write_raw)
                    *(float2*)(raw_out + off) = make_float2(v0, v1);
                v0 = fmaxf(v0, 0.f);
                v1 = fmaxf(v1, 0.f);
                __nv_bfloat16 h0, l0, h1, l1;
                split_bf16(v0, h0, l0);
                split_bf16(v1, h1, l1);
                uint32_t hp = (uint32_t)__bfloat16_as_ushort(h0)
                            | ((uint32_t)__bfloat16_as_ushort(h1) << 16);
                uint32_t lp = (uint32_t)__bfloat16_as_ushort(l0)
                            | ((uint32_t)__bfloat16_as_ushort(l1) << 16);
                *(uint32_t*)(Ohi + off) = hp;
                *(uint32_t*)(Olo + off) = lp;
            }
        }
    }
}

// ---- prep: relu + bf16 hi/lo split of x -------------------------------------
__global__ void prep_split_relu(const float* __restrict__ src,
                                __nv_bfloat16* __restrict__ hi,
                                __nv_bfloat16* __restrict__ lo, int n)
{
    int t = blockIdx.x * blockDim.x + threadIdx.x;
    if (t >= n) return;
    float v = fmaxf(src[t], 0.0f);
    __nv_bfloat16 h, l;
    split_bf16(v, h, l);
    hi[t] = h; lo[t] = l;
}

// ---- prep: transpose W[K,N] -> Wt[N,K] + bf16 hi/lo split -------------------
__global__ void prep_w(const float* __restrict__ W,
                       __nv_bfloat16* __restrict__ hi,
                       __nv_bfloat16* __restrict__ lo, int K, int N)
{
    int t = blockIdx.x * blockDim.x + threadIdx.x;
    if (t >= K * N) return;
    int k = t / N, n = t % N;
    float v = W[t];
    __nv_bfloat16 h, l;
    split_bf16(v, h, l);
    size_t d = (size_t)n * K + k;
    hi[d] = h; lo[d] = l;
}

// ---- final: logit = (hi+lo) . SW2[p] + Sb2[p]; sigmoid/clip/ratio/mask ------
__global__ void subnet_final(const __nv_bfloat16* __restrict__ s1h,
                             const __nv_bfloat16* __restrict__ s1l,
                             const float* __restrict__ SW2,
                             const float* __restrict__ Sb2,
                             const int*   __restrict__ y,
                             const int*   __restrict__ pairs,
                             int p,
                             float* __restrict__ out_r,
                             float* __restrict__ out_s,
                             float* __restrict__ out_m,
                             int Nrows)
{
    __shared__ float w[256];
    const int tid = threadIdx.x;
    w[tid] = SW2[p * 256 + tid];
    __syncthreads();

    const float sb = Sb2[p];
    const int pa = pairs[2 * p + 0];
    const int pb = pairs[2 * p + 1];

    const int lane = tid & 31;
    const int warp = tid >> 5;
    const int gw = blockIdx.x * (blockDim.x >> 5) + warp;
    const int warps_total = gridDim.x * (blockDim.x >> 5);

    for (int n = gw; n < Nrows; n += warps_total) {
        const size_t base = (size_t)n * 256;
        float acc = 0.f;
#pragma unroll
        for (int j = 0; j < 8; j++) {
            int c = lane + 32 * j;
            float v = __bfloat162float(s1h[base + c]) + __bfloat162float(s1l[base + c]);
            acc += v * w[c];
        }
#pragma unroll
        for (int o = 16; o > 0; o >>= 1)
            acc += __shfl_xor_sync(0xFFFFFFFFu, acc, o);

        if (lane == 0) {
            float logit = acc + sb;
            float s = 1.f / (1.f + expf(-logit));
            s = fmaxf(s, 1e-9f);
            float r = (1.f - s) / s;
            int yv = y[n];
            float m = (yv == pa || yv == pb) ? 1.f : 0.f;
            out_r[n] = r * m;
            out_s[n] = s * m;
            out_m[n] = m;
        }
    }
}

// ============================================================================
extern "C" void kernel_launch(void* const* d_in, const int* in_sizes, int n_in,
                              void* d_out, int out_size)
{
    const float* x     = (const float*)d_in[0];
    const int*   y     = (const int*)  d_in[1];
    const int*   pairs = (const int*)  d_in[2];
    const float* W0    = (const float*)d_in[3];
    const float* b0    = (const float*)d_in[4];
    const float* W1    = (const float*)d_in[5];
    const float* b1    = (const float*)d_in[6];
    const float* W2    = (const float*)d_in[7];
    const float* b2    = (const float*)d_in[8];
    const float* SW0   = (const float*)d_in[9];
    const float* Sb0   = (const float*)d_in[10];
    const float* SW1   = (const float*)d_in[11];
    const float* Sb1   = (const float*)d_in[12];
    const float* SW2   = (const float*)d_in[13];
    const float* Sb2   = (const float*)d_in[14];

    const int M = GN;
    float* out   = (float*)d_out;
    float* repr  = out;
    float* r_seg = out + (size_t)M * 512;
    float* s_seg = r_seg + 3 * (size_t)M;
    float* m_seg = s_seg + 3 * (size_t)M;

    __nv_bfloat16 *hiA, *loA, *hiB, *loB, *hiC, *loC, *hiX, *loX, *whi, *wlo;
    cudaGetSymbolAddress((void**)&hiA, g_hiA);
    cudaGetSymbolAddress((void**)&loA, g_loA);
    cudaGetSymbolAddress((void**)&hiB, g_hiB);
    cudaGetSymbolAddress((void**)&loB, g_loB);
    cudaGetSymbolAddress((void**)&hiC, g_hiC);
    cudaGetSymbolAddress((void**)&loC, g_loC);
    cudaGetSymbolAddress((void**)&hiX, g_hiX);
    cudaGetSymbolAddress((void**)&loX, g_loX);
    cudaGetSymbolAddress((void**)&whi, g_whi);
    cudaGetSymbolAddress((void**)&wlo, g_wlo);

    cudaFuncSetAttribute(gemm_mma, cudaFuncAttributeMaxDynamicSharedMemorySize,
                         2 * STAGE_BYTES);

    // ---- weight / input prep ------------------------------------------------
    prep_split_relu<<<(M * 64 + 255) / 256, 256>>>(x, hiX, loX, M * 64);
    prep_w<<<(64 * 512 + 255) / 256, 256>>>(W0, whi + OFF_W0, wlo + OFF_W0, 64, 512);
    prep_w<<<(512 * 512 + 255) / 256, 256>>>(W1, whi + OFF_W1, wlo + OFF_W1, 512, 512);
    prep_w<<<(512 * 512 + 255) / 256, 256>>>(W2, whi + OFF_W2, wlo + OFF_W2, 512, 512);
    for (int p = 0; p < 3; p++) {
        prep_w<<<(512 * 512 + 255) / 256, 256>>>(SW0 + (size_t)p * 512 * 512,
            whi + OFF_SW0 + p * 262144u, wlo + OFF_SW0 + p * 262144u, 512, 512);
        prep_w<<<(512 * 256 + 255) / 256, 256>>>(SW1 + (size_t)p * 512 * 256,
            whi + OFF_SW1 + p * 131072u, wlo + OFF_SW1 + p * 131072u, 512, 256);
    }

    dim3 blk(256);
    dim3 g512(4, M / 128);
    dim3 g256(2, M / 128);
    const size_t shmem = 2 * STAGE_BYTES;

    // trunk
    gemm_mma<<<g512, blk, shmem>>>(hiX, loX, whi + OFF_W0, wlo + OFF_W0, b0,
                                   nullptr, hiA, loA, 64, 512, 0);
    gemm_mma<<<g512, blk, shmem>>>(hiA, loA, whi + OFF_W1, wlo + OFF_W1, b1,
                                   nullptr, hiB, loB, 512, 512, 0);
    gemm_mma<<<g512, blk, shmem>>>(hiB, loB, whi + OFF_W2, wlo + OFF_W2, b2,
                                   repr, hiA, loA, 512, 512, 1);

    // subnets
    for (int p = 0; p < 3; p++) {
        gemm_mma<<<g512, blk, shmem>>>(hiA, loA,
            whi + OFF_SW0 + p * 262144u, wlo + OFF_SW0 + p * 262144u,
            Sb0 + p * 512, nullptr, hiB, loB, 512, 512, 0);
        gemm_mma<<<g256, blk, shmem>>>(hiB, loB,
            whi + OFF_SW1 + p * 131072u, wlo + OFF_SW1 + p * 131072u,
            Sb1 + p * 256, nullptr, hiC, loC, 512, 256, 0);
        subnet_final<<<512, 256>>>(hiC, loC, SW2, Sb2, y, pairs, p,
                                   r_seg + (size_t)p * M,
                                   s_seg + (size_t)p * M,
                                   m_seg + (size_t)p * M, M);
    }
}